// round 9
// baseline (speedup 1.0000x reference)
#include <cuda_runtime.h>

// Problem constants
#define B_   2
#define T_   8
#define BT_  16
#define NQ_  128
#define NK_  128
#define DIN_ 64
#define DOUT_ 256
#define DC_  64      // d-values per staged chunk
#define KPITCH_ 68   // words per K row (68 % 32 == 4 -> conflict-free LDS.128)

// Device-global scratch: tanh of projected Q / K (fp32)
__device__ float g_Q[B_ * NQ_ * DOUT_];       // tq = tanh(query @ Wq)
__device__ float g_K[BT_ * NK_ * DOUT_];      // tk = tanh(keys @ Wk + bk)

__device__ __forceinline__ float ftanh(float x) {
    float r;
    asm("tanh.approx.f32 %0, %1;" : "=f"(r) : "f"(x));
    return r;
}
__device__ __forceinline__ float frcp(float x) {
    float r;
    asm("rcp.approx.f32 %0, %1;" : "=f"(r) : "f"(x));
    return r;
}

// ---------------------------------------------------------------------------
// Kernel 1: projections + tanh (fp32).
// Grid = 32 Q + 256 K = 288 blocks (8 rows), 2 blocks/SM.
// W register double-buffered to hide L2 latency. tanh applied at store.
// ---------------------------------------------------------------------------
__global__ void __launch_bounds__(256, 2) proj_kernel(
    const float* __restrict__ query, const float* __restrict__ keys,
    const float* __restrict__ Wq,    const float* __restrict__ Wk,
    const float* __restrict__ bk)
{
    __shared__ float in_sh[8][DIN_];

    const int blk = blockIdx.x;            // 0..287
    const bool isQ = (blk < 32);
    const int r0 = (isQ ? blk : (blk - 32)) * 8;
    const float* __restrict__ in = isQ ? query : keys;
    const float* __restrict__ W  = isQ ? Wq    : Wk;
    float* __restrict__ outb     = isQ ? g_Q   : g_K;

    const int tid = threadIdx.x;
    const int cg = tid & 63;                // cols 4*cg..4*cg+3
    const int rg = tid >> 6;                // rows rg*2, rg*2+1

    if (tid < 128) {
        const int r = tid >> 4, s = tid & 15;
        *(float4*)&in_sh[r][s * 4] =
            *(const float4*)(in + (size_t)(r0 + r) * DIN_ + s * 4);
    }
    __syncthreads();

    float4 bias = make_float4(0.f, 0.f, 0.f, 0.f);
    if (!isQ) bias = *(const float4*)(bk + cg * 4);

    float4 acc0 = bias, acc1 = bias;
    const int row0 = rg * 2, row1 = rg * 2 + 1;

    float4 wcur[8], wnxt[8];
#pragma unroll
    for (int i = 0; i < 8; i++)
        wcur[i] = *(const float4*)(W + (size_t)i * DOUT_ + cg * 4);

#pragma unroll
    for (int ic = 0; ic < 8; ic++) {
        if (ic < 7) {
#pragma unroll
            for (int i = 0; i < 8; i++)
                wnxt[i] = *(const float4*)(W + (size_t)((ic + 1) * 8 + i) * DOUT_ + cg * 4);
        }
#pragma unroll
        for (int i = 0; i < 8; i++) {
            const float x0 = in_sh[row0][ic * 8 + i];
            const float x1 = in_sh[row1][ic * 8 + i];
            acc0.x = fmaf(x0, wcur[i].x, acc0.x);
            acc0.y = fmaf(x0, wcur[i].y, acc0.y);
            acc0.z = fmaf(x0, wcur[i].z, acc0.z);
            acc0.w = fmaf(x0, wcur[i].w, acc0.w);
            acc1.x = fmaf(x1, wcur[i].x, acc1.x);
            acc1.y = fmaf(x1, wcur[i].y, acc1.y);
            acc1.z = fmaf(x1, wcur[i].z, acc1.z);
            acc1.w = fmaf(x1, wcur[i].w, acc1.w);
        }
#pragma unroll
        for (int i = 0; i < 8; i++) wcur[i] = wnxt[i];
    }

    // Apply tanh at store: downstream uses the addition identity.
    float4 t0 = make_float4(ftanh(acc0.x), ftanh(acc0.y), ftanh(acc0.z), ftanh(acc0.w));
    float4 t1 = make_float4(ftanh(acc1.x), ftanh(acc1.y), ftanh(acc1.z), ftanh(acc1.w));
    *(float4*)&outb[(size_t)(r0 + row0) * DOUT_ + cg * 4] = t0;
    *(float4*)&outb[(size_t)(r0 + row1) * DOUT_ + cg * 4] = t1;
}

// ---------------------------------------------------------------------------
// Kernel 2: scores via tanh addition identity + fused softmax.
//   tanh(q+k) = (tq + tk) / (1 + tq*tk)   [exact identity]
// Per element: FMA(den) + FADD(num) + MUFU.RCP + FMUL + FMA(acc)
//   -> FMA pipe 28.3K cyc/SMSP, MUFU 28.3K cyc/SMSP: balanced saturation.
// Grid 256 blocks (bt x 16 q-chunks of 8) x 256 thr. Warp w -> q row q0+w;
// lane owns nk {l, l+32, l+64, l+96}. K staged in 4 chunks of 64 d
// (pitch-68 -> conflict-free LDS.128). Softmax fused per warp.
// ---------------------------------------------------------------------------
__global__ void __launch_bounds__(256, 2) attn_kernel(
    const float* __restrict__ v, float* __restrict__ out)
{
    __shared__ float k_sh[NK_ * KPITCH_];      // 34.8 KB
    __shared__ float q_sh[8][DC_];             // 2 KB
    __shared__ float v_sh[DC_];                // 256 B

    const int bt = blockIdx.x >> 4;            // 0..15
    const int q0 = (blockIdx.x & 15) << 3;     // q chunk of 8
    const int b  = bt >> 3;

    const int tid  = threadIdx.x;
    const int w    = tid >> 5;
    const int lane = tid & 31;

    const float* __restrict__ kbase = g_K + (size_t)(bt * NK_) * DOUT_;
    const float* __restrict__ qbase = g_Q + (size_t)(b * NQ_ + q0) * DOUT_;

    float accA = 0.f, accB = 0.f, accC = 0.f, accD = 0.f;

#pragma unroll 1
    for (int c = 0; c < DOUT_ / DC_; c++) {
        const int d0 = c * DC_;

        // Stage K chunk: 128 rows x 16 float4 (8 per thread), pitch 68
#pragma unroll
        for (int e = tid; e < NK_ * 16; e += 256) {
            const int nk = e >> 4, s = e & 15;
            float4 t = *(const float4*)(kbase + (size_t)nk * DOUT_ + d0 + s * 4);
            *(float4*)&k_sh[nk * KPITCH_ + s * 4] = t;
        }
        // Stage Q chunk: 8 rows x 16 float4
        if (tid < 128) {
            const int r = tid >> 4, s = tid & 15;
            *(float4*)&q_sh[r][s * 4] =
                *(const float4*)(qbase + (size_t)r * DOUT_ + d0 + s * 4);
        }
        // Stage v chunk
        if (tid >= 128 && tid < 144) {
            const int s = tid - 128;
            *(float4*)&v_sh[s * 4] = *(const float4*)(v + d0 + s * 4);
        }
        __syncthreads();

        const float* __restrict__ kAp = &k_sh[(lane      ) * KPITCH_];
        const float* __restrict__ kBp = &k_sh[(lane + 32 ) * KPITCH_];
        const float* __restrict__ kCp = &k_sh[(lane + 64 ) * KPITCH_];
        const float* __restrict__ kDp = &k_sh[(lane + 96 ) * KPITCH_];

#pragma unroll 4
        for (int d4 = 0; d4 < DC_; d4 += 4) {
            // Front-load this 4-d group: 6 x LDS.128
            float4 kA = *(const float4*)(kAp + d4);
            float4 kB = *(const float4*)(kBp + d4);
            float4 kC = *(const float4*)(kCp + d4);
            float4 kD = *(const float4*)(kDp + d4);
            float4 qv = *(const float4*)&q_sh[w][d4];
            float4 vv = *(const float4*)&v_sh[d4];

#pragma unroll
            for (int j = 0; j < 4; j++) {
                const float tq = (j == 0) ? qv.x : (j == 1) ? qv.y
                               : (j == 2) ? qv.z : qv.w;
                const float vd = (j == 0) ? vv.x : (j == 1) ? vv.y
                               : (j == 2) ? vv.z : vv.w;
                const float tkA = (j == 0) ? kA.x : (j == 1) ? kA.y
                                : (j == 2) ? kA.z : kA.w;
                const float tkB = (j == 0) ? kB.x : (j == 1) ? kB.y
                                : (j == 2) ? kB.z : kB.w;
                const float tkC = (j == 0) ? kC.x : (j == 1) ? kC.y
                                : (j == 2) ? kC.z : kC.w;
                const float tkD = (j == 0) ? kD.x : (j == 1) ? kD.y
                                : (j == 2) ? kD.z : kD.w;

                const float rA = frcp(fmaf(tq, tkA, 1.0f));
                const float rB = frcp(fmaf(tq, tkB, 1.0f));
                const float rC = frcp(fmaf(tq, tkC, 1.0f));
                const float rD = frcp(fmaf(tq, tkD, 1.0f));

                accA = fmaf(vd, (tq + tkA) * rA, accA);
                accB = fmaf(vd, (tq + tkB) * rB, accB);
                accC = fmaf(vd, (tq + tkC) * rC, accC);
                accD = fmaf(vd, (tq + tkD) * rD, accD);
            }
        }
        __syncthreads();
    }

    // Fused softmax over nk (warp owns the full 128-wide row)
    float m = fmaxf(fmaxf(accA, accB), fmaxf(accC, accD));
#pragma unroll
    for (int o = 16; o > 0; o >>= 1)
        m = fmaxf(m, __shfl_xor_sync(0xffffffffu, m, o));

    const float eA = __expf(accA - m);
    const float eB = __expf(accB - m);
    const float eC = __expf(accC - m);
    const float eD = __expf(accD - m);
    float ssum = eA + eB + eC + eD;
#pragma unroll
    for (int o = 16; o > 0; o >>= 1)
        ssum += __shfl_xor_sync(0xffffffffu, ssum, o);

    const float rinv = 1.0f / ssum;

    float* __restrict__ orow = out + (size_t)(bt * NQ_ + q0 + w) * NK_;
    orow[lane      ] = eA * rinv;
    orow[lane + 32 ] = eB * rinv;
    orow[lane + 64 ] = eC * rinv;
    orow[lane + 96 ] = eD * rinv;
}

// ---------------------------------------------------------------------------
extern "C" void kernel_launch(void* const* d_in, const int* in_sizes, int n_in,
                              void* d_out, int out_size)
{
    const float* query = (const float*)d_in[0];
    const float* keys  = (const float*)d_in[1];
    const float* Wq    = (const float*)d_in[2];
    const float* Wk    = (const float*)d_in[3];
    const float* bk    = (const float*)d_in[4];
    const float* v     = (const float*)d_in[5];
    float* out = (float*)d_out;

    proj_kernel<<<288, 256>>>(query, keys, Wq, Wk, bk);
    attn_kernel<<<256, 256>>>(v, out);
}